// round 5
// baseline (speedup 1.0000x reference)
#include <cuda_runtime.h>
#include <stdint.h>

#define N_STEPS 50

// Output layout (flattened tuple, row-major, float32):
//   slot0 = Xn history [32,50,64,8]      @ 0          (post-sample state)
//   slot1 = En history [32,50,64,64,5]   @ 819200     (post-sample state)
//   slot2 = Xc history [32,50,64,8]      @ 33587200   (pre-step state)
//   slot3 = Ec history [32,50,64,64,5]   @ 34406400   (pre-step state)
#define OFF_EN  819200
#define OFF_XC  33587200
#define OFF_EC  34406400

// Per-step derived keys (partitionable split) + precomputed log-prob tables.
__device__ uint2 g_kx[N_STEPS];
__device__ uint2 g_ke[N_STEPS];
__device__ float g_lqe[N_STEPS * 25];   // [k][l][c], D=5
__device__ float g_lqx[N_STEPS * 64];   // [k][l][c], D=8

// ---------------- Threefry-2x32 (JAX-exact: 20 rounds, 5 key injections) ----
__device__ __forceinline__ void tf2x32(uint32_t k0, uint32_t k1,
                                       uint32_t x0, uint32_t x1,
                                       uint32_t& o0, uint32_t& o1) {
    uint32_t ks2 = k0 ^ k1 ^ 0x1BD11BDAu;
    x0 += k0; x1 += k1;
#define TF_R(r) { x0 += x1; x1 = __funnelshift_l(x1, x1, (r)); x1 ^= x0; }
    TF_R(13) TF_R(15) TF_R(26) TF_R(6)
    x0 += k1;  x1 += ks2 + 1u;
    TF_R(17) TF_R(29) TF_R(16) TF_R(24)
    x0 += ks2; x1 += k0 + 2u;
    TF_R(13) TF_R(15) TF_R(26) TF_R(6)
    x0 += k0;  x1 += k1 + 3u;
    TF_R(17) TF_R(29) TF_R(16) TF_R(24)
    x0 += k1;  x1 += ks2 + 4u;
    TF_R(13) TF_R(15) TF_R(26) TF_R(6)
    x0 += ks2; x1 += k0 + 5u;
#undef TF_R
    o0 = x0; o1 = x1;
}

// Partitionable random_bits(32): element i -> XOR of both cipher words of
// block (hi,lo) = (0, i).
__device__ __forceinline__ uint32_t jax_bits32(uint2 key, uint32_t idx) {
    uint32_t o0, o1;
    tf2x32(key.x, key.y, 0u, idx, o0, o1);
    return o0 ^ o1;
}

// JAX gumbel from raw bits.
__device__ __forceinline__ float gumbel_from_bits(uint32_t bits) {
    const float TINY = 1.17549435082228751e-38f;
    float u = __uint_as_float((bits >> 9) | 0x3f800000u) - 1.0f;
    u = u + TINY;
    u = fmaxf(TINY, u);
    return -logf(-logf(u));
}

// ------- init: per-step keys (fold_in + partitionable split) + logq tables ---
template <int D>
__device__ __forceinline__ void make_logq(const float* __restrict__ W,
                                          float gamma, float* __restrict__ dst) {
    for (int l = 0; l < D; l++) {
        const float* row = W + l * D;
        float p[D];
        float m = row[0];
        for (int c = 1; c < D; c++) m = fmaxf(m, row[c]);
        float s = 0.0f;
        for (int c = 0; c < D; c++) { p[c] = expf(row[c] - m); s += p[c]; }
        for (int c = 0; c < D; c++) p[c] = (p[c] / s) * gamma;
        p[l] = 0.0f;
        float s2 = 0.0f;
        for (int c = 0; c < D; c++) s2 += p[c];
        p[l] = fmaxf(1.0f - s2, 0.0f);
        float t = 0.0f;
        for (int c = 0; c < D; c++) t += p[c];
        for (int c = 0; c < D; c++) dst[l * D + c] = logf(p[c] / t);
    }
}

__global__ void init_kernel(const float* __restrict__ gammas,
                            const float* __restrict__ Wx,
                            const float* __restrict__ We) {
    int k = threadIdx.x;
    if (k >= N_STEPS) return;
    uint32_t f0, f1;
    tf2x32(0u, 42u, 0u, (uint32_t)k, f0, f1);        // fold_in(key(42), k)
    uint32_t a0, a1, b0, b1;
    tf2x32(f0, f1, 0u, 0u, a0, a1);                  // split key[0]
    tf2x32(f0, f1, 0u, 1u, b0, b1);                  // split key[1]
    g_kx[k] = make_uint2(a0, a1);
    g_ke[k] = make_uint2(b0, b1);

    float gamma = gammas[k];
    make_logq<5>(We, gamma, &g_lqe[k * 25]);
    make_logq<8>(Wx, gamma, &g_lqx[k * 64]);
}

// node_mask dtype detection (bool8 / int32 / float32).
__device__ __forceinline__ int detect_mask_mode(const void* p) {
    const unsigned char* u = (const unsigned char*)p;
    if (u[1] == 1) return 0;
    if (((const int*)p)[0] == 1) return 1;
    return 2;
}
__device__ __forceinline__ bool mask_val(const void* p, int mode, int idx) {
    if (mode == 0) return ((const unsigned char*)p)[idx] != 0;
    if (mode == 1) return ((const int*)p)[idx] != 0;
    return ((const float*)p)[idx] != 0.0f;
}

// ---------------------------- main kernel -----------------------------------
// Blocks 0..511: edge chains (one thread per (b,i,j); 131072 threads)
// Blocks 512..519: node chains (one thread per (b,i); 2048 threads)
__global__ __launch_bounds__(256)
void langevin_main(const float* __restrict__ X, const float* __restrict__ E,
                   const void* __restrict__ maskp,
                   float* __restrict__ out) {
    __shared__ uint2 sKey[N_STEPS];
    __shared__ float sLq[N_STEPS * 64];
    __shared__ int sMode;

    const bool edge = blockIdx.x < 512;
    if (edge) {
        for (int t = threadIdx.x; t < N_STEPS; t += 256) sKey[t] = g_ke[t];
        for (int t = threadIdx.x; t < N_STEPS * 25; t += 256) sLq[t] = g_lqe[t];
    } else {
        for (int t = threadIdx.x; t < N_STEPS; t += 256) sKey[t] = g_kx[t];
        for (int t = threadIdx.x; t < N_STEPS * 64; t += 256) sLq[t] = g_lqx[t];
    }
    if (threadIdx.x == 0) sMode = detect_mask_mode(maskp);
    __syncthreads();
    const int mode = sMode;

    if (edge) {
        int tid = blockIdx.x * 256 + threadIdx.x;      // 0..131071
        int b = tid >> 12;
        int ij = tid & 4095;
        int i = ij >> 6, j = ij & 63;
        bool valid = (i != j) && mask_val(maskp, mode, b * 64 + i)
                              && mask_val(maskp, mode, b * 64 + j);
        int lo = (i < j) ? i : j;
        int hi = (i < j) ? j : i;
        uint32_t gbase = (uint32_t)(((b * 64 + lo) * 64 + hi) * 5);

        float in[5];
        const float* ep = E + ((size_t)b * 4096 + ij) * 5;
#pragma unroll
        for (int c = 0; c < 5; c++) in[c] = ep[c];

        // post-sample (En) -> slot1; pre-step (Ec) -> slot3
        float* postE = out + OFF_EN + (size_t)b * 50 * 20480 + (size_t)ij * 5;
        float* preE  = out + OFF_EC + (size_t)b * 50 * 20480 + (size_t)ij * 5;

        if (valid) {
            int l = 0;
            float bv = in[0];
#pragma unroll
            for (int c = 1; c < 5; c++) if (in[c] > bv) { bv = in[c]; l = c; }
#pragma unroll 1
            for (int k = 0; k < N_STEPS; k++) {
                float* pp = preE  + (size_t)k * 20480;
                float* sp = postE + (size_t)k * 20480;
                // pre-step state: input at k=0 (raw), else previous one-hot
                if (k == 0) {
#pragma unroll
                    for (int c = 0; c < 5; c++) pp[c] = in[c];
                } else {
#pragma unroll
                    for (int c = 0; c < 5; c++) pp[c] = (c == l) ? 1.0f : 0.0f;
                }
                uint2 key = sKey[k];
                const float* lq = &sLq[k * 25 + l * 5];
                float best = 0.0f;
                int bi = 0;
#pragma unroll
                for (int c = 0; c < 5; c++) {
                    float g = gumbel_from_bits(jax_bits32(key, gbase + c));
                    float sc = lq[c] + g;
                    if (c == 0) best = sc;
                    else if (sc > best) { best = sc; bi = c; }
                }
                l = bi;
#pragma unroll
                for (int c = 0; c < 5; c++) sp[c] = (c == l) ? 1.0f : 0.0f;
            }
        } else {
            // masked or diagonal: pre = input at k=0 else 0; post = 0 always
#pragma unroll 2
            for (int k = 0; k < N_STEPS; k++) {
                float* pp = preE  + (size_t)k * 20480;
                float* sp = postE + (size_t)k * 20480;
#pragma unroll
                for (int c = 0; c < 5; c++) pp[c] = (k == 0) ? in[c] : 0.0f;
#pragma unroll
                for (int c = 0; c < 5; c++) sp[c] = 0.0f;
            }
        }
    } else {
        int t = (blockIdx.x - 512) * 256 + threadIdx.x;  // 0..2047
        int b = t >> 6, i = t & 63;
        bool valid = mask_val(maskp, mode, b * 64 + i);
        uint32_t gbase = (uint32_t)((b * 64 + i) * 8);

        float in[8];
        const float* xp = X + (size_t)(b * 64 + i) * 8;
#pragma unroll
        for (int c = 0; c < 8; c++) in[c] = xp[c];

        // post-sample (Xn) -> slot0; pre-step (Xc) -> slot2
        float* postX = out + (size_t)b * 50 * 512 + (size_t)i * 8;
        float* preX  = out + OFF_XC + (size_t)b * 50 * 512 + (size_t)i * 8;

        if (valid) {
            int l = 0;
            float bv = in[0];
#pragma unroll
            for (int c = 1; c < 8; c++) if (in[c] > bv) { bv = in[c]; l = c; }
#pragma unroll 1
            for (int k = 0; k < N_STEPS; k++) {
                float* pp = preX  + (size_t)k * 512;
                float* sp = postX + (size_t)k * 512;
                if (k == 0) {
#pragma unroll
                    for (int c = 0; c < 8; c++) pp[c] = in[c];
                } else {
#pragma unroll
                    for (int c = 0; c < 8; c++) pp[c] = (c == l) ? 1.0f : 0.0f;
                }
                uint2 key = sKey[k];
                const float* lq = &sLq[k * 64 + l * 8];
                float best = 0.0f;
                int bi = 0;
#pragma unroll
                for (int c = 0; c < 8; c++) {
                    float g = gumbel_from_bits(jax_bits32(key, gbase + c));
                    float sc = lq[c] + g;
                    if (c == 0) best = sc;
                    else if (sc > best) { best = sc; bi = c; }
                }
                l = bi;
#pragma unroll
                for (int c = 0; c < 8; c++) sp[c] = (c == l) ? 1.0f : 0.0f;
            }
        } else {
#pragma unroll 2
            for (int k = 0; k < N_STEPS; k++) {
                float* pp = preX  + (size_t)k * 512;
                float* sp = postX + (size_t)k * 512;
#pragma unroll
                for (int c = 0; c < 8; c++) pp[c] = (k == 0) ? in[c] : 0.0f;
#pragma unroll
                for (int c = 0; c < 8; c++) sp[c] = 0.0f;
            }
        }
    }
}

extern "C" void kernel_launch(void* const* d_in, const int* in_sizes, int n_in,
                              void* d_out, int out_size) {
    (void)in_sizes; (void)n_in; (void)out_size;
    const float* X      = (const float*)d_in[0];
    const float* E      = (const float*)d_in[1];
    const void*  maskp  = d_in[2];
    const float* gammas = (const float*)d_in[3];
    const float* Wx     = (const float*)d_in[4];
    const float* We     = (const float*)d_in[5];

    init_kernel<<<1, 64>>>(gammas, Wx, We);
    langevin_main<<<520, 256>>>(X, E, maskp, (float*)d_out);
}